// round 8
// baseline (speedup 1.0000x reference)
#include <cuda_runtime.h>
#include <math.h>

// ---------------- problem constants ----------------
#define Bsz    16
#define CIN    103
#define CCONV  256
#define NOUT   103
#define DOUT   16
#define RECN   8343            // 9*9*103
#define H1N    5562
#define H2N    12514
#define F0N    1648            // NOUT*DOUT
#define NCH    15              // conv ci-chunks (7 channels each)

// ---------------- scratch (device globals; no allocation) ----------------
__device__ float g_wT[927 * 256];              // transposed conv weights [e=ci*9+k][co]
__device__ float g_Wsum[CCONV * NOUT * DOUT];  // sum over prim axis of W_caps
__device__ float g_part[Bsz * NCH * CCONV * 49];
__device__ float g_hsum[Bsz * CCONV * 49];     // relu'd conv activations
__device__ float g_sq[Bsz * CCONV];
__device__ float g_bij[NOUT * CCONV];
__device__ float g_sj[Bsz * NOUT * DOUT];
__device__ float g_v[Bsz * NOUT * DOUT];
__device__ float g_f0[Bsz * F0N];
__device__ float g_f1[Bsz * H1N];
__device__ float g_f2[Bsz * H2N];
__device__ float g_fcpart[33 * Bsz * H2N];     // k-split partials (max S=33)

// packed f32x2 FMA (sm_103a FFMA2 — PTX-only, ptxas never auto-fuses)
#define FMA_F32X2(acc, a, b) \
    asm("fma.rn.f32x2 %0, %1, %2, %0;" : "+l"(acc) : "l"(a), "l"(b))
#define PACK2(dst, w) \
    asm("mov.b64 %0, {%1, %1};" : "=l"(dst) : "f"(w))

// ---------------- small prep kernels ----------------

// conv-weight transpose + routing-logit init fused
__global__ void k_prep(const float* __restrict__ w) {
    int idx = blockIdx.x * 256 + threadIdx.x;
    if (idx < 927 * 256) {
        int e = idx >> 8, co = idx & 255;
        g_wT[idx] = w[co * 927 + e];
    } else {
        int r = idx - 927 * 256;
        if (r < NOUT * CCONV) g_bij[r] = 1.0f;
    }
}

__global__ void k_wsum(const float* __restrict__ Wc) {
    int idx = blockIdx.x * 256 + threadIdx.x;        // 256*103*16
    if (idx < CCONV * NOUT * DOUT) {
        const float4* p = (const float4*)(Wc + (size_t)idx * 32);
        float s = 0.f;
#pragma unroll
        for (int i = 0; i < 8; i++) {
            float4 v = p[i];
            s += v.x + v.y + v.z + v.w;
        }
        g_Wsum[idx] = s;
    }
}

// ---------------- conv ----------------
// partial sums over pixel range [PH0,PH1]: grid (NCH, 16), 256 threads = co
template<int PH0, int PH1>
__global__ void __launch_bounds__(256, 3) k_conv_t(const float* __restrict__ x) {
    int chunk = blockIdx.x, b = blockIdx.y;
    int ci0 = chunk * 7;
    int cnt = min(7, CIN - ci0);
    __shared__ float xs[7 * 81];
    const float* xp = x + (b * CIN + ci0) * 81;
    for (int i = threadIdx.x; i < cnt * 81; i += 256) xs[i] = xp[i];
    __syncthreads();

    int co = threadIdx.x;
    constexpr int NP = (PH1 - PH0 + 1) * 7;
    float acc[NP];
#pragma unroll
    for (int p = 0; p < NP; p++) acc[p] = 0.f;

    float wA[9], wB[9];
#pragma unroll
    for (int k = 0; k < 9; k++) wA[k] = g_wT[(ci0 * 9 + k) * 256 + co];

    for (int cl = 0; cl < cnt; cl++) {
        if (cl + 1 < cnt) {
#pragma unroll
            for (int k = 0; k < 9; k++)
                wB[k] = g_wT[((ci0 + cl + 1) * 9 + k) * 256 + co];
        }
        const float* xr0 = &xs[cl * 81];
#pragma unroll
        for (int r = PH0; r <= PH1 + 2; r++) {
            float xr[9];
#pragma unroll
            for (int q = 0; q < 9; q++) xr[q] = xr0[r * 9 + q];
#pragma unroll
            for (int kh = 0; kh < 3; kh++) {
                int ph = r - kh;
                if (ph >= PH0 && ph <= PH1) {
#pragma unroll
                    for (int pw = 0; pw < 7; pw++) {
#pragma unroll
                        for (int kw = 0; kw < 3; kw++)
                            acc[(ph - PH0) * 7 + pw] =
                                fmaf(wA[kh * 3 + kw], xr[pw + kw], acc[(ph - PH0) * 7 + pw]);
                    }
                }
            }
        }
#pragma unroll
        for (int k = 0; k < 9; k++) wA[k] = wB[k];
    }
    float* outp = &g_part[((b * NCH + chunk) * 256 + co) * 49];
#pragma unroll
    for (int p = 0; p < NP; p++) outp[PH0 * 7 + p] = acc[p];
}

// wide chunk-sum + bias + relu: one thread per (b,co,pix) = 200704
__global__ void k_relu_sum(const float* __restrict__ conv_b) {
    int idx = blockIdx.x * 256 + threadIdx.x;
    if (idx < Bsz * CCONV * 49) {
        int pix = idx % 49;
        int co  = (idx / 49) & 255;
        int b   = idx / (49 * 256);
        float s = conv_b[co];
#pragma unroll
        for (int ch = 0; ch < NCH; ch++)
            s += g_part[(size_t)((b * NCH + ch) * 256 + co) * 49 + pix];
        g_hsum[idx] = fmaxf(s, 0.f);
    }
}

// mean over pixels + squash over channels
__global__ void k_squash_p() {
    int b = blockIdx.x;
    int co = threadIdx.x;
    const float* hp = &g_hsum[(b * 256 + co) * 49];
    float acc = 0.f;
#pragma unroll
    for (int pix = 0; pix < 49; pix++) acc += hp[pix];
    float p = acc * (1.f / 49.f);

    __shared__ float red[256];
    red[co] = p * p;
    __syncthreads();
    for (int st = 128; st > 0; st >>= 1) {
        if (co < st) red[co] += red[co + st];
        __syncthreads();
    }
    float msq = red[0];
    float sq = p * msq / ((1.f + msq) * sqrtf(msq));
    g_sq[b * 256 + co] = sq;
}

// ---------------- routing ----------------

__global__ void __launch_bounds__(256) k_route_sj() {
    int j = blockIdx.x;
    int t = threadIdx.x;
    __shared__ float cs[256];
    __shared__ float csq[16 * 256];
    __shared__ float ws[256 * 16];
    __shared__ float red[256];

    float bv = g_bij[j * 256 + t];
    red[t] = bv;
    __syncthreads();
    for (int st = 128; st > 0; st >>= 1) {
        if (t < st) red[t] = fmaxf(red[t], red[t + st]);
        __syncthreads();
    }
    float mx = red[0];
    __syncthreads();
    float e = expf(bv - mx);
    red[t] = e;
    __syncthreads();
    for (int st = 128; st > 0; st >>= 1) {
        if (t < st) red[t] += red[t + st];
        __syncthreads();
    }
    float denom = red[0];
    cs[t] = e / denom;
    for (int i = t; i < 256 * 16; i += 256) {
        int c = i >> 4, o = i & 15;
        ws[i] = g_Wsum[c * (NOUT * DOUT) + j * DOUT + o];
    }
    __syncthreads();
    for (int i = t; i < 16 * 256; i += 256)
        csq[i] = cs[i & 255] * g_sq[i];
    __syncthreads();

    int b = t >> 4, o = t & 15;
    const float* cq = &csq[b * 256];
    float acc = 0.f;
#pragma unroll 8
    for (int c = 0; c < 256; c++)
        acc = fmaf(cq[c], ws[c * 16 + o], acc);
    g_sj[(b * NOUT + j) * DOUT + o] = acc;
}

__global__ void k_route_v() {
    int b = blockIdx.x;
    int t = threadIdx.x;
    int o = t & 15, part = t >> 4;
    __shared__ float red[256];
    float s = 0.f;
    for (int j = part; j < NOUT; j += 16) {
        float v = g_sj[(b * NOUT + j) * DOUT + o];
        s += v * v;
    }
    red[t] = s;
    __syncthreads();
    for (int st = 128; st >= 16; st >>= 1) {
        if (t < st) red[t] += red[t + st];
        __syncthreads();
    }
    float msq = red[o];
    float scale = msq / ((1.f + msq) * sqrtf(msq));
    for (int j = part; j < NOUT; j += 16) {
        int i = (b * NOUT + j) * DOUT + o;
        g_v[i] = scale * g_sj[i];
    }
}

__global__ void k_route_update() {
    int j = blockIdx.x;
    int c = threadIdx.x;
    __shared__ float vs[16 * 16];
    if (c < 256) {
        int b = c >> 4, o = c & 15;
        vs[c] = g_v[(b * NOUT + j) * DOUT + o];
    }
    __syncthreads();
    const float4* w4 = (const float4*)&g_Wsum[(c * NOUT + j) * DOUT];
    float4 wa = w4[0], wb = w4[1], wc = w4[2], wd = w4[3];
    float w[16] = {wa.x, wa.y, wa.z, wa.w, wb.x, wb.y, wb.z, wb.w,
                   wc.x, wc.y, wc.z, wc.w, wd.x, wd.y, wd.z, wd.w};
    float q = 0.f;
#pragma unroll
    for (int b = 0; b < 16; b++) {
        float dot = 0.f;
#pragma unroll
        for (int o = 0; o < 16; o++) dot = fmaf(w[o], vs[b * 16 + o], dot);
        q = fmaf(g_sq[b * 256 + c], dot, q);
    }
    g_bij[j * 256 + c] += q * (1.f / 16.f);
}

__global__ void k_ba_f0(float* __restrict__ out) {
    int idx = blockIdx.x * 256 + threadIdx.x;   // 1648
    if (idx < Bsz * NOUT) {
        int b = idx / NOUT, j = idx % NOUT;
        const float* vp = &g_v[(b * NOUT + j) * DOUT];
        float msq = 0.f;
#pragma unroll
        for (int o = 0; o < 16; o++) msq = fmaf(vp[o], vp[o], msq);
        float ba = sqrtf(msq);
        out[b * NOUT + j] = ba;
        float* f0 = &g_f0[b * F0N + j * 16];
#pragma unroll
        for (int o = 0; o < 16; o++) f0[o] = vp[o] * ba;
    }
}

// ---------------- FC GEMM ----------------
// 4 columns per thread (stride 256), 16 batches -> 32 u64 FMA2 accumulators.
// 2-deep software-pipelined weight prefetch (streaming loads).
// g_fcpart[s][b][n] = sum_{k in chunk s} fin[b][k] * W[k][n]
__global__ void __launch_bounds__(256, 2) k_gemm4(int fin_sel,
                                                  const float* __restrict__ W,
                                                  int N, int K, int kchunk) {
    const float* fin = (fin_sel == 0) ? g_f0 : (fin_sel == 1) ? g_f1 : g_f2;
    int s = blockIdx.y;
    int nb = blockIdx.x * 1024 + threadIdx.x;
    int k0 = s * kchunk;
    int k1 = min(K, k0 + kchunk);

    int nc[4];
    bool vld[4];
#pragma unroll
    for (int c = 0; c < 4; c++) {
        int n = nb + c * 256;
        vld[c] = (n < N);
        nc[c] = vld[c] ? n : 0;    // clamp keeps loads in-bounds; store guarded
    }

    __shared__ __align__(16) float fs[128 * 16];   // [kk][b]
    unsigned long long acc[32];
#pragma unroll
    for (int p = 0; p < 32; p++) acc[p] = 0ull;

    for (int kt = k0; kt < k1; kt += 128) {
        int kc = min(128, k1 - kt);
        __syncthreads();
        for (int i = threadIdx.x; i < 16 * 128; i += 256) {
            int b = i >> 7, kk = i & 127;
            if (kk < kc) fs[kk * 16 + b] = fin[b * K + kt + kk];
        }
        __syncthreads();

        const float* wp = W + (size_t)kt * N;
        // pipeline prologue: rows 0 and 1
        float a0, a1, a2, a3, b0, b1, b2, b3;
        {
            const float* r0 = wp;
            a0 = __ldcs(r0 + nc[0]); a1 = __ldcs(r0 + nc[1]);
            a2 = __ldcs(r0 + nc[2]); a3 = __ldcs(r0 + nc[3]);
            const float* r1 = wp + (size_t)((1 < kc) ? 1 : 0) * N;
            b0 = __ldcs(r1 + nc[0]); b1 = __ldcs(r1 + nc[1]);
            b2 = __ldcs(r1 + nc[2]); b3 = __ldcs(r1 + nc[3]);
        }
        for (int kk = 0; kk < kc; kk += 2) {
            // prefetch kk+2 / kk+3 (clamped in-bounds)
            float c0, c1, c2, c3, d0, d1, d2, d3;
            {
                int kp2 = (kk + 2 < kc) ? kk + 2 : kc - 1;
                int kp3 = (kk + 3 < kc) ? kk + 3 : kc - 1;
                const float* r2 = wp + (size_t)kp2 * N;
                const float* r3 = wp + (size_t)kp3 * N;
                c0 = __ldcs(r2 + nc[0]); c1 = __ldcs(r2 + nc[1]);
                c2 = __ldcs(r2 + nc[2]); c3 = __ldcs(r2 + nc[3]);
                d0 = __ldcs(r3 + nc[0]); d1 = __ldcs(r3 + nc[1]);
                d2 = __ldcs(r3 + nc[2]); d3 = __ldcs(r3 + nc[3]);
            }
            // compute kk
            {
                const ulonglong2* f4 = (const ulonglong2*)&fs[kk * 16];
                ulonglong2 q0 = f4[0], q1 = f4[1], q2 = f4[2], q3 = f4[3];
                unsigned long long p0, p1, p2, p3;
                PACK2(p0, a0); PACK2(p1, a1); PACK2(p2, a2); PACK2(p3, a3);
                FMA_F32X2(acc[0],  p0, q0.x); FMA_F32X2(acc[1],  p0, q0.y);
                FMA_F32X2(acc[2],  p0, q1.x); FMA_F32X2(acc[3],  p0, q1.y);
                FMA_F32X2(acc[4],  p0, q2.x); FMA_F32X2(acc[5],  p0, q2.y);
                FMA_F32X2(acc[6],  p0, q3.x); FMA_F32X2(acc[7],  p0, q3.y);
                FMA_F32X2(acc[8],  p1, q0.x); FMA_F32X2(acc[9],  p1, q0.y);
                FMA_F32X2(acc[10], p1, q1.x); FMA_F32X2(acc[11], p1, q1.y);
                FMA_F32X2(acc[12], p1, q2.x); FMA_F32X2(acc[13], p1, q2.y);
                FMA_F32X2(acc[14], p1, q3.x); FMA_F32X2(acc[15], p1, q3.y);
                FMA_F32X2(acc[16], p2, q0.x); FMA_F32X2(acc[17], p2, q0.y);
                FMA_F32X2(acc[18], p2, q1.x); FMA_F32X2(acc[19], p2, q1.y);
                FMA_F32X2(acc[20], p2, q2.x); FMA_F32X2(acc[21], p2, q2.y);
                FMA_F32X2(acc[22], p2, q3.x); FMA_F32X2(acc[23], p2, q3.y);
                FMA_F32X2(acc[24], p3, q0.x); FMA_F32X2(acc[25], p3, q0.y);
                FMA_F32X2(acc[26], p3, q1.x); FMA_F32X2(acc[27], p3, q1.y);
                FMA_F32X2(acc[28], p3, q2.x); FMA_F32X2(acc[29], p3, q2.y);
                FMA_F32X2(acc[30], p3, q3.x); FMA_F32X2(acc[31], p3, q3.y);
            }
            // compute kk+1
            if (kk + 1 < kc) {
                const ulonglong2* f4 = (const ulonglong2*)&fs[(kk + 1) * 16];
                ulonglong2 q0 = f4[0], q1 = f4[1], q2 = f4[2], q3 = f4[3];
                unsigned long long p0, p1, p2, p3;
                PACK2(p0, b0); PACK2(p1, b1); PACK2(p2, b2); PACK2(p3, b3);
                FMA_F32X2(acc[0],  p0, q0.x); FMA_F32X2(acc[1],  p0, q0.y);
                FMA_F32X2(acc[2],  p0, q1.x); FMA_F32X2(acc[3],  p0, q1.y);
                FMA_F32X2(acc[4],  p0, q2.x); FMA_F32X2(acc[5],  p0, q2.y);
                FMA_F32X2(acc[6],  p0, q3.x); FMA_F32X2(acc[7],  p0, q3.y);
                FMA_F32X2(acc[8],  p1, q0.x); FMA_F32X2(acc[9],  p1, q0.y);
                FMA_F32X2(acc[10], p1, q1.x); FMA_F32X2(acc[11], p1, q1.y);
                FMA_F32X2(acc[12], p1, q2.x); FMA_F32X2(acc[13], p1, q2.y);
                FMA_F32X2(acc[14], p1, q3.x); FMA_F32X2(acc[15], p1, q3.y);
                FMA_F32X2(acc[16], p2, q0.x); FMA_F32X2(acc[17], p2, q0.y);
                FMA_F32X2(acc[18], p2, q1.x); FMA_F32X2(acc[19], p2, q1.y);
                FMA_F32X2(acc[20], p2, q2.x); FMA_F32X2(acc[21], p2, q2.y);
                FMA_F32X2(acc[22], p2, q3.x); FMA_F32X2(acc[23], p2, q3.y);
                FMA_F32X2(acc[24], p3, q0.x); FMA_F32X2(acc[25], p3, q0.y);
                FMA_F32X2(acc[26], p3, q1.x); FMA_F32X2(acc[27], p3, q1.y);
                FMA_F32X2(acc[28], p3, q2.x); FMA_F32X2(acc[29], p3, q2.y);
                FMA_F32X2(acc[30], p3, q3.x); FMA_F32X2(acc[31], p3, q3.y);
            }
            a0 = c0; a1 = c1; a2 = c2; a3 = c3;
            b0 = d0; b1 = d1; b2 = d2; b3 = d3;
        }
    }

#pragma unroll
    for (int c = 0; c < 4; c++) {
        if (vld[c]) {
#pragma unroll
            for (int p = 0; p < 8; p++) {
                unsigned long long a = acc[c * 8 + p];
                float lo = __uint_as_float((unsigned int)a);
                float hi = __uint_as_float((unsigned int)(a >> 32));
                g_fcpart[(size_t)(s * 16 + 2 * p + 0) * N + nc[c]] = lo;
                g_fcpart[(size_t)(s * 16 + 2 * p + 1) * N + nc[c]] = hi;
            }
        }
    }
}

// deterministic k-split reduction + bias.
// out_sel: 0 -> g_f1, 1 -> g_f2, 2 -> harness out pointer (recon region)
__global__ void k_reduce(const float* __restrict__ bias,
                         int N, int S, int out_sel, float* __restrict__ hout) {
    float* out = (out_sel == 0) ? g_f1 : (out_sel == 1) ? g_f2 : hout;
    int idx = blockIdx.x * 256 + threadIdx.x;
    if (idx < 16 * N) {
        int b = idx / N, n = idx - b * N;
        float s = bias[n];
        for (int sp = 0; sp < S; sp++) s += g_fcpart[(size_t)(sp * 16 + b) * N + n];
        out[b * N + n] = s;
    }
}

// ---------------- launcher ----------------
extern "C" void kernel_launch(void* const* d_in, const int* in_sizes, int n_in,
                              void* d_out, int out_size) {
    const float* x      = (const float*)d_in[0];
    const float* conv_w = (const float*)d_in[1];
    const float* conv_b = (const float*)d_in[2];
    const float* W_caps = (const float*)d_in[3];
    const float* fc1_w  = (const float*)d_in[4];
    const float* fc1_b  = (const float*)d_in[5];
    const float* fc2_w  = (const float*)d_in[6];
    const float* fc2_b  = (const float*)d_in[7];
    const float* fc3_w  = (const float*)d_in[8];
    const float* fc3_b  = (const float*)d_in[9];
    float* out = (float*)d_out;

    (void)in_sizes; (void)n_in; (void)out_size;

    k_prep<<<(927 * 256 + NOUT * CCONV + 255) / 256, 256>>>(conv_w);
    k_wsum<<<1648, 256>>>(W_caps);
    k_conv_t<0, 3><<<dim3(NCH, 16), 256>>>(x);
    k_conv_t<4, 6><<<dim3(NCH, 16), 256>>>(x);
    k_relu_sum<<<(Bsz * CCONV * 49 + 255) / 256, 256>>>(conv_b);
    k_squash_p<<<16, 256>>>();

    for (int it = 0; it < 3; it++) {
        k_route_sj<<<103, 256>>>();
        k_route_v<<<16, 256>>>();
        if (it < 2) k_route_update<<<103, 256>>>();
    }
    k_ba_f0<<<7, 256>>>(out);

    // fc1: (16x1648)@(1648x5562)   tiles=6,  S=26 (chunk 64)  -> 156 blocks
    k_gemm4<<<dim3(6, 26), 256>>>(0, fc1_w, H1N, F0N, 64);
    k_reduce<<<(16 * H1N + 255) / 256, 256>>>(fc1_b, H1N, 26, 0, out);
    // fc2: (16x5562)@(5562x12514)  tiles=13, S=23 (chunk 242) -> 299 blocks
    k_gemm4<<<dim3(13, 23), 256>>>(1, fc2_w, H2N, H1N, 242);
    k_reduce<<<(16 * H2N + 255) / 256, 256>>>(fc2_b, H2N, 23, 1, out);
    // fc3: (16x12514)@(12514x8343) tiles=9,  S=33 (chunk 380) -> 297 blocks
    k_gemm4<<<dim3(9, 33), 256>>>(2, fc3_w, RECN, H2N, 380);
    k_reduce<<<(16 * RECN + 255) / 256, 256>>>(fc3_b, RECN, 33, 2, out + Bsz * NOUT);
}